// round 7
// baseline (speedup 1.0000x reference)
#include <cuda_runtime.h>
#include <cuda_fp16.h>
#include <math.h>

#define N_NODES 100000
#define D 64
#define E_MAX 1600000
#define NB 296            // persistent-kernel blocks (2/SM at 256thr — co-resident)
#define NT 256
#define CHUNK 1024
#define NCHUNK ((N_NODES + CHUNK - 1) / CHUNK)   // 98

// ---- scratch (__device__ globals: allocation-free per harness rules) ----
__device__ __half g_mH[(size_t)N_NODES * D];    // fp16 message buffer (GEMM out)
__device__ __half g_hH[(size_t)N_NODES * D];    // fp16 hidden state
__device__ float  g_r[N_NODES];                 // per-node scalar (layer-3 collapse)
__device__ float  g_ws[D];                      // colsum(W3)
__device__ float  g_bsum[1];                    // sum(b3)
__device__ int    g_cnt[N_NODES];
__device__ int    g_rowptr[N_NODES];
__device__ int    g_cursor[N_NODES];
__device__ int    g_eidx[E_MAX];
__device__ int    g_csum[128];                  // chunk totals
__device__ int    g_coff[128];                  // chunk offsets
__device__ int    g_bar[8];                     // grid-barrier counters (zero-init;
                                                // reset by final_kernel each call)

// ---- side stream + events for graph fork (created at load; never freed) ----
static cudaStream_t g_s2;
static cudaEvent_t  g_evFork, g_evJoin;
static bool g_streamOk = [](){
    if (cudaStreamCreateWithFlags(&g_s2, cudaStreamNonBlocking) != cudaSuccess) return false;
    if (cudaEventCreateWithFlags(&g_evFork, cudaEventDisableTiming) != cudaSuccess) return false;
    if (cudaEventCreateWithFlags(&g_evJoin, cudaEventDisableTiming) != cudaSuccess) return false;
    return true;
}();

// ============================ fused CSR build (persistent) ============================

// Every thread fences its own writes (device scope), block syncs, then one
// thread arrives and spins. Canonical threadFenceReduction pattern.
__device__ __forceinline__ void grid_barrier(int idx) {
    __threadfence();
    __syncthreads();
    if (threadIdx.x == 0) {
        atomicAdd(&g_bar[idx], 1);
        while (*(volatile int*)&g_bar[idx] < NB) __nanosleep(64);
    }
    __syncthreads();
}

__global__ __launch_bounds__(NT) void csr_build_kernel(const int* __restrict__ src,
                                                       const int* __restrict__ dst,
                                                       const float* __restrict__ W3,
                                                       const float* __restrict__ b3,
                                                       float* __restrict__ out, int out_n,
                                                       int E) {
    const int bid = blockIdx.x, t = threadIdx.x;
    const int gid = bid * NT + t;
    const int gstride = NB * NT;

    // ---- phase Z: zero g_cnt; block 0 also computes constants & zeroes d_out ----
    for (int i = gid; i < N_NODES; i += gstride) g_cnt[i] = 0;
    if (bid == 0) {
        if (t < D) {
            float s = 0.f;
#pragma unroll
            for (int j = 0; j < D; j++) s += W3[j * D + t];
            g_ws[t] = s;
        } else if (t == D) {
            float bs = 0.f;
#pragma unroll
            for (int j = 0; j < D; j++) bs += b3[j];
            g_bsum[0] = bs;
        } else if (t >= 96 && t < 96 + out_n) {
            out[t - 96] = 0.f;
        }
    }
    grid_barrier(0);

    // ---- phase D: degree histogram ----
    for (int e = gid; e < E; e += gstride) atomicAdd(&g_cnt[dst[e]], 1);
    grid_barrier(1);

    // ---- phase S: per-chunk exclusive scan (blocks 0..NCHUNK-1; barriers
    //      are block-wide and non-divergent inside those blocks) ----
    if (bid < NCHUNK) {
        int base = bid * CHUNK + t * 4;
        int c[4];
        int ts = 0;
#pragma unroll
        for (int i = 0; i < 4; i++) {
            int idx = base + i;
            c[i] = (idx < N_NODES) ? __ldcg(&g_cnt[idx]) : 0;
            ts += c[i];
        }
        int lane = t & 31, wid = t >> 5;
        int incl = ts;
#pragma unroll
        for (int d = 1; d < 32; d <<= 1) {
            int u = __shfl_up_sync(0xffffffffu, incl, d);
            if (lane >= d) incl += u;
        }
        __shared__ int wsum[8], woff[8];
        if (lane == 31) wsum[wid] = incl;
        __syncthreads();
        if (t == 0) {
            int acc = 0;
#pragma unroll
            for (int i = 0; i < 8; i++) { woff[i] = acc; acc += wsum[i]; }
            g_csum[bid] = acc;   // chunk total
        }
        __syncthreads();
        int excl = incl - ts + woff[wid];    // exclusive within chunk
#pragma unroll
        for (int i = 0; i < 4; i++) {
            int idx = base + i;
            if (idx < N_NODES) g_rowptr[idx] = excl;
            excl += c[i];
        }
    }
    grid_barrier(2);

    // ---- phase S2: block 0 scans the chunk totals.
    //      ALL 256 threads execute every __syncthreads (work is guarded). ----
    if (bid == 0) {
        __shared__ int sm[128];
        int v = 0;
        if (t < 128) {
            v = (t < NCHUNK) ? __ldcg(&g_csum[t]) : 0;
            sm[t] = v;
        }
        __syncthreads();
        for (int d = 1; d < 128; d <<= 1) {
            int add = (t < 128 && t >= d) ? sm[t - d] : 0;
            __syncthreads();
            if (t < 128) sm[t] += add;
            __syncthreads();
        }
        if (t < NCHUNK) g_coff[t] = sm[t] - v;   // exclusive
    }
    grid_barrier(3);

    // ---- phase A: add chunk offsets; init cursors ----
    for (int i = gid; i < N_NODES; i += gstride) {
        int v = __ldcg(&g_rowptr[i]) + __ldcg(&g_coff[i >> 10]);
        g_rowptr[i] = v;
        g_cursor[i] = v;
    }
    grid_barrier(4);

    // ---- phase F: fill CSR adjacency ----
    for (int e = gid; e < E; e += gstride) {
        int pos = atomicAdd(&g_cursor[dst[e]], 1);
        if ((unsigned)pos < (unsigned)E) g_eidx[pos] = src[e];  // insurance, never hot
    }
}

// ============================ register-blocked GEMM ============================
// out[row] = in[row] @ W^T + b, fp16 output. 256 thr, 128 rows x 64 cols/block.
template<bool HALF_IN>
__global__ __launch_bounds__(256) void gemm_rb_kernel(const void* __restrict__ in_,
                                                      const float* __restrict__ W,
                                                      const float* __restrict__ b,
                                                      __half2* __restrict__ out) {
    __shared__ float inT[D][128];   // 32KB, [k][row]
    __shared__ float Ws[D * D];     // 16KB
    __shared__ float bs[D];
    int t = threadIdx.x;
    for (int i = t; i < D * D; i += 256) Ws[i] = W[i];
    if (t < D) bs[t] = b[t];

    int row0 = blockIdx.x * 128;
    int r = t >> 1, half = t & 1;
    int grow = row0 + r;
    if (HALF_IN) {
        const __half2* inH = (const __half2*)in_ + (size_t)grow * 32 + half * 16;
        if (grow < N_NODES) {
#pragma unroll
            for (int i = 0; i < 16; i++) {
                float2 f = __half22float2(inH[i]);
                inT[half * 32 + 2 * i + 0][r] = f.x;
                inT[half * 32 + 2 * i + 1][r] = f.y;
            }
        } else {
#pragma unroll
            for (int i = 0; i < 32; i++) inT[half * 32 + i][r] = 0.f;
        }
    } else {
        const float4* inF = (const float4*)((const float*)in_ + (size_t)grow * D + half * 32);
        if (grow < N_NODES) {
#pragma unroll
            for (int i = 0; i < 8; i++) {
                float4 v = inF[i];
                inT[half * 32 + 4 * i + 0][r] = v.x;
                inT[half * 32 + 4 * i + 1][r] = v.y;
                inT[half * 32 + 4 * i + 2][r] = v.z;
                inT[half * 32 + 4 * i + 3][r] = v.w;
            }
        } else {
#pragma unroll
            for (int i = 0; i < 32; i++) inT[half * 32 + i][r] = 0.f;
        }
    }
    __syncthreads();

    int w = t >> 5, l = t & 31;
    int colBase = w * 8;
    float acc[4][8];
#pragma unroll
    for (int i = 0; i < 4; i++)
#pragma unroll
        for (int j = 0; j < 8; j++) acc[i][j] = 0.f;

#pragma unroll 4
    for (int k = 0; k < D; k++) {
        float4 a = *(const float4*)&inT[k][l * 4];
#pragma unroll
        for (int jj = 0; jj < 8; jj++) {
            float wv = Ws[(colBase + jj) * D + k];
            acc[0][jj] += a.x * wv;
            acc[1][jj] += a.y * wv;
            acc[2][jj] += a.z * wv;
            acc[3][jj] += a.w * wv;
        }
    }

#pragma unroll
    for (int i = 0; i < 4; i++) {
        int orow = row0 + l * 4 + i;
        if (orow < N_NODES) {
            __half2 o[4];
#pragma unroll
            for (int j = 0; j < 4; j++)
                o[j] = __floats2half2_rn(acc[i][2 * j]     + bs[colBase + 2 * j],
                                         acc[i][2 * j + 1] + bs[colBase + 2 * j + 1]);
            *(uint4*)&out[(size_t)orow * 32 + colBase / 2] = *(const uint4*)o;
        }
    }
}

// ============================ aggregation kernels ============================

__global__ __launch_bounds__(256) void agg_kernel(const __half2* __restrict__ m,
                                                  __half2* __restrict__ out) {
    int node = (blockIdx.x * blockDim.x + threadIdx.x) >> 5;
    int l = threadIdx.x & 31;
    if (node >= N_NODES) return;
    int start = g_rowptr[node];
    int n = g_cnt[node];
    float a0 = 0.f, a1 = 0.f, b0 = 0.f, b1 = 0.f;
    float c0 = 0.f, c1 = 0.f, d0 = 0.f, d1 = 0.f;
    int k = 0;
    for (; k + 4 <= n; k += 4) {
        int s0 = __ldg(g_eidx + start + k + 0);
        int s1 = __ldg(g_eidx + start + k + 1);
        int s2 = __ldg(g_eidx + start + k + 2);
        int s3 = __ldg(g_eidx + start + k + 3);
        float2 v0 = __half22float2(__ldg(m + (size_t)s0 * 32 + l));
        float2 v1 = __half22float2(__ldg(m + (size_t)s1 * 32 + l));
        float2 v2 = __half22float2(__ldg(m + (size_t)s2 * 32 + l));
        float2 v3 = __half22float2(__ldg(m + (size_t)s3 * 32 + l));
        a0 += v0.x; a1 += v0.y;
        b0 += v1.x; b1 += v1.y;
        c0 += v2.x; c1 += v2.y;
        d0 += v3.x; d1 += v3.y;
    }
    for (; k < n; k++) {
        int s = __ldg(g_eidx + start + k);
        float2 v = __half22float2(__ldg(m + (size_t)s * 32 + l));
        a0 += v.x; a1 += v.y;
    }
    float v0 = (a0 + b0) + (c0 + d0);
    float v1 = (a1 + b1) + (c1 + d1);
    out[(size_t)node * 32 + l] = __floats2half2_rn(tanhf(v0), tanhf(v1));
}

__global__ __launch_bounds__(256) void agg_rsum_kernel(const __half2* __restrict__ m) {
    int node = (blockIdx.x * blockDim.x + threadIdx.x) >> 5;
    int l = threadIdx.x & 31;
    if (node >= N_NODES) return;
    int start = g_rowptr[node];
    int n = g_cnt[node];
    float a0 = 0.f, a1 = 0.f, b0 = 0.f, b1 = 0.f;
    float c0 = 0.f, c1 = 0.f, d0 = 0.f, d1 = 0.f;
    int k = 0;
    for (; k + 4 <= n; k += 4) {
        int s0 = __ldg(g_eidx + start + k + 0);
        int s1 = __ldg(g_eidx + start + k + 1);
        int s2 = __ldg(g_eidx + start + k + 2);
        int s3 = __ldg(g_eidx + start + k + 3);
        float2 v0 = __half22float2(__ldg(m + (size_t)s0 * 32 + l));
        float2 v1 = __half22float2(__ldg(m + (size_t)s1 * 32 + l));
        float2 v2 = __half22float2(__ldg(m + (size_t)s2 * 32 + l));
        float2 v3 = __half22float2(__ldg(m + (size_t)s3 * 32 + l));
        a0 += v0.x; a1 += v0.y;
        b0 += v1.x; b1 += v1.y;
        c0 += v2.x; c1 += v2.y;
        d0 += v3.x; d1 += v3.y;
    }
    for (; k < n; k++) {
        int s = __ldg(g_eidx + start + k);
        float2 v = __half22float2(__ldg(m + (size_t)s * 32 + l));
        a0 += v.x; a1 += v.y;
    }
    float v0 = (a0 + b0) + (c0 + d0);
    float v1 = (a1 + b1) + (c1 + d1);
    float s = tanhf(v0) * g_ws[2 * l] + tanhf(v1) * g_ws[2 * l + 1];
#pragma unroll
    for (int off = 16; off; off >>= 1) s += __shfl_down_sync(0xffffffffu, s, off);
    if (l == 0) g_r[node] = s + g_bsum[0];
}

// final: per node, sum r over incoming edges (CSR), bin by graph.
// Also resets the grid-barrier counters for the next replay (stream-ordered).
__global__ __launch_bounds__(256) void final_kernel(const int* __restrict__ n2g,
                                                    float* __restrict__ out) {
    __shared__ float bins[8];
    int t = threadIdx.x;
    if (t < 8) bins[t] = 0.f;
    if (blockIdx.x == 0 && t < 8) g_bar[t] = 0;
    __syncthreads();
    int node = (blockIdx.x * blockDim.x + t) >> 5;
    int l = t & 31;
    if (node < N_NODES) {
        int start = g_rowptr[node], n = g_cnt[node];
        float s = 0.f;
        for (int e = l; e < n; e += 32) s += __ldg(g_r + __ldg(g_eidx + start + e));
#pragma unroll
        for (int off = 16; off; off >>= 1) s += __shfl_down_sync(0xffffffffu, s, off);
        if (l == 0) atomicAdd(&bins[__ldg(n2g + node)], s);
    }
    __syncthreads();
    if (t < 8) atomicAdd(&out[t], bins[t]);
}

// ============================ launch ============================

extern "C" void kernel_launch(void* const* d_in, const int* in_sizes, int n_in,
                              void* d_out, int out_size) {
    const float* x   = (const float*)d_in[0];
    const float* W1  = (const float*)d_in[1];
    const float* b1  = (const float*)d_in[2];
    const float* W2  = (const float*)d_in[3];
    const float* b2  = (const float*)d_in[4];
    const float* W3  = (const float*)d_in[5];
    const float* b3  = (const float*)d_in[6];
    const int*   src = (const int*)d_in[7];
    const int*   dst = (const int*)d_in[8];
    const int*   n2g = (const int*)d_in[9];
    float* out = (float*)d_out;

    int E = in_sizes[7];

    int gemm_blocks = (N_NODES + 127) / 128;
    int warp_blocks = (N_NODES * 32 + 255) / 256;

    __half* mH;  __half* hH;
    cudaGetSymbolAddress((void**)&mH, g_mH);
    cudaGetSymbolAddress((void**)&hH, g_hH);

    if (g_streamOk) {
        // fork: gemm1 on side stream, fused CSR build on main stream
        cudaEventRecord(g_evFork, 0);
        cudaStreamWaitEvent(g_s2, g_evFork, 0);
        gemm_rb_kernel<false><<<gemm_blocks, 256, 0, g_s2>>>(x, W1, b1, (__half2*)mH);
        cudaEventRecord(g_evJoin, g_s2);

        csr_build_kernel<<<NB, NT>>>(src, dst, W3, b3, out, out_size, E);

        cudaStreamWaitEvent(0, g_evJoin, 0);   // join before agg1
    } else {
        csr_build_kernel<<<NB, NT>>>(src, dst, W3, b3, out, out_size, E);
        gemm_rb_kernel<false><<<gemm_blocks, 256>>>(x, W1, b1, (__half2*)mH);
    }

    agg_kernel<<<warp_blocks, 256>>>((const __half2*)mH, (__half2*)hH);
    gemm_rb_kernel<true><<<gemm_blocks, 256>>>(hH, W2, b2, (__half2*)mH);
    agg_rsum_kernel<<<warp_blocks, 256>>>((const __half2*)mH);
    final_kernel<<<warp_blocks, 256>>>(n2g, out);
}

// round 8
// speedup vs baseline: 1.4112x; 1.4112x over previous
#include <cuda_runtime.h>
#include <cuda_fp16.h>
#include <math.h>

#define N_NODES 100000
#define D 64
#define E_MAX 1600000
#define CHUNK 1024
#define NCHUNK ((N_NODES + CHUNK - 1) / CHUNK)   // 98

// ---- scratch (__device__ globals: allocation-free per harness rules) ----
__device__ __half g_mH[(size_t)N_NODES * D];    // fp16 message buffer (GEMM out)
__device__ __half g_hH[(size_t)N_NODES * D];    // fp16 hidden state
__device__ float  g_r[N_NODES];                 // per-node scalar (layer-3 collapse)
__device__ float  g_ws[D];                      // colsum(W3)
__device__ float  g_bsum[1];                    // sum(b3)
__device__ int    g_cnt[N_NODES];
__device__ int    g_rowptr[N_NODES];
__device__ int    g_cursor[N_NODES];
__device__ int    g_eidx[E_MAX];
__device__ int    g_csum[128];                  // lookback publish slots (+1 encoded)

// ---- side stream + events for graph fork (created at load; never freed) ----
static cudaStream_t g_s2;
static cudaEvent_t  g_evFork, g_evJoin;
static bool g_streamOk = [](){
    if (cudaStreamCreateWithFlags(&g_s2, cudaStreamNonBlocking) != cudaSuccess) return false;
    if (cudaEventCreateWithFlags(&g_evFork, cudaEventDisableTiming) != cudaSuccess) return false;
    if (cudaEventCreateWithFlags(&g_evJoin, cudaEventDisableTiming) != cudaSuccess) return false;
    return true;
}();

// ---- packed f32x2 helpers (Blackwell FFMA2; PTX-only per SASS_QUICKREF) ----
__device__ __forceinline__ void fma_x2(unsigned long long& acc,
                                       unsigned long long a, unsigned long long b) {
    asm("fma.rn.f32x2 %0, %1, %2, %0;" : "+l"(acc) : "l"(a), "l"(b));
}
__device__ __forceinline__ unsigned long long bcast_x2(float v) {
    unsigned long long r;
    asm("mov.b64 %0, {%1, %1};" : "=l"(r) : "r"(__float_as_uint(v)));
    return r;
}
__device__ __forceinline__ float2 unpack_x2(unsigned long long v) {
    unsigned int lo, hi;
    asm("mov.b64 {%0, %1}, %2;" : "=r"(lo), "=r"(hi) : "l"(v));
    return make_float2(__uint_as_float(lo), __uint_as_float(hi));
}

// ============================ init (fused) ============================
__global__ void init_kernel(const float* __restrict__ W3, const float* __restrict__ b3,
                            float* __restrict__ out, int out_n) {
    int t = threadIdx.x;
    if (blockIdx.x == 0) {
        if (t < D) {
            float s = 0.f;
#pragma unroll
            for (int j = 0; j < D; j++) s += W3[j * D + t];
            g_ws[t] = s;
        } else if (t == D) {
            float bs = 0.f;
#pragma unroll
            for (int j = 0; j < D; j++) bs += b3[j];
            g_bsum[0] = bs;
        } else if (t >= 96 && t < 96 + out_n) {
            out[t - 96] = 0.f;
        } else if (t >= 128) {
            g_csum[t - 128] = 0;
        }
    } else {
        int i = (blockIdx.x - 1) * blockDim.x + t;
        if (i < N_NODES) g_cnt[i] = 0;
    }
}

__global__ void degree_kernel(const int* __restrict__ dst, int E) {
    int e = blockIdx.x * blockDim.x + threadIdx.x;
    if (e < E) atomicAdd(&g_cnt[dst[e]], 1);   // no return -> REDG
}

// single-pass exclusive scan with decoupled lookback (98 blocks, wave-1 resident)
__global__ __launch_bounds__(256) void scanapply_kernel() {
    int b = blockIdx.x, t = threadIdx.x;
    int base = b * CHUNK + t * 4;
    int c[4];
    int ts = 0;
#pragma unroll
    for (int i = 0; i < 4; i++) {
        int idx = base + i;
        c[i] = (idx < N_NODES) ? g_cnt[idx] : 0;
        ts += c[i];
    }
    int lane = t & 31, wid = t >> 5;
    int incl = ts;
#pragma unroll
    for (int d = 1; d < 32; d <<= 1) {
        int u = __shfl_up_sync(0xffffffffu, incl, d);
        if (lane >= d) incl += u;
    }
    __shared__ int wsum[8], woff[8];
    __shared__ int rsum[8];
    __shared__ int s_prefix;
    if (lane == 31) wsum[wid] = incl;
    __syncthreads();
    if (t == 0) {
        int acc = 0;
#pragma unroll
        for (int i = 0; i < 8; i++) { woff[i] = acc; acc += wsum[i]; }
        *(volatile int*)&g_csum[b] = acc + 1;   // publish (+1: 0 = not ready)
    }
    __syncthreads();
    int part = 0;
    if (t < b) {
        volatile int* p = &g_csum[t];
        int v;
        do { v = *p; } while (v == 0);
        part = v - 1;
    }
#pragma unroll
    for (int off = 16; off; off >>= 1) part += __shfl_down_sync(0xffffffffu, part, off);
    if (lane == 0) rsum[wid] = part;
    __syncthreads();
    if (t == 0) {
        int acc = 0;
#pragma unroll
        for (int i = 0; i < 8; i++) acc += rsum[i];
        s_prefix = acc;
    }
    __syncthreads();
    int excl = incl - ts + woff[wid] + s_prefix;
#pragma unroll
    for (int i = 0; i < 4; i++) {
        int idx = base + i;
        if (idx < N_NODES) { g_rowptr[idx] = excl; g_cursor[idx] = excl; }
        excl += c[i];
    }
}

__global__ void fill_kernel(const int* __restrict__ src, const int* __restrict__ dst, int E) {
    int e = blockIdx.x * blockDim.x + threadIdx.x;
    if (e < E) {
        int pos = atomicAdd(&g_cursor[dst[e]], 1);
        g_eidx[pos] = src[e];
    }
}

// ============================ f32x2 register-blocked GEMM ============================
// out[row] = in[row] @ W^T + b, fp16 output. 256 thr, 128 rows x 64 cols/block,
// thread = 4 rows x 8 cols. Weights staged TRANSPOSED (WsT[k][j]) so a broadcast
// LDS.64 yields a packed column-pair; math is packed fma.rn.f32x2 (16/k-step).
template<bool HALF_IN>
__global__ __launch_bounds__(256) void gemm_rb_kernel(const void* __restrict__ in_,
                                                      const float* __restrict__ W,
                                                      const float* __restrict__ b,
                                                      __half2* __restrict__ out) {
    __shared__ float inT[D][128];        // 32KB, [k][row]
    __shared__ float WsT[D][D + 2];      // ~16.5KB, [k][col] (transposed, padded)
    __shared__ float bs[D];
    int t = threadIdx.x;
    for (int i = t; i < D * D; i += 256) {
        int j = i >> 6, k = i & 63;
        WsT[k][j] = W[i];                // W row-major [j][k] -> WsT[k][j]
    }
    if (t < D) bs[t] = b[t];

    int row0 = blockIdx.x * 128;
    int r = t >> 1, half = t & 1;
    int grow = row0 + r;
    if (HALF_IN) {
        const __half2* inH = (const __half2*)in_ + (size_t)grow * 32 + half * 16;
        if (grow < N_NODES) {
#pragma unroll
            for (int i = 0; i < 16; i++) {
                float2 f = __half22float2(inH[i]);
                inT[half * 32 + 2 * i + 0][r] = f.x;
                inT[half * 32 + 2 * i + 1][r] = f.y;
            }
        } else {
#pragma unroll
            for (int i = 0; i < 32; i++) inT[half * 32 + i][r] = 0.f;
        }
    } else {
        const float4* inF = (const float4*)((const float*)in_ + (size_t)grow * D + half * 32);
        if (grow < N_NODES) {
#pragma unroll
            for (int i = 0; i < 8; i++) {
                float4 v = inF[i];
                inT[half * 32 + 4 * i + 0][r] = v.x;
                inT[half * 32 + 4 * i + 1][r] = v.y;
                inT[half * 32 + 4 * i + 2][r] = v.z;
                inT[half * 32 + 4 * i + 3][r] = v.w;
            }
        } else {
#pragma unroll
            for (int i = 0; i < 32; i++) inT[half * 32 + i][r] = 0.f;
        }
    }
    __syncthreads();

    int w = t >> 5, l = t & 31;
    int colBase = w * 8;
    unsigned long long acc[4][4];        // [row][colpair], packed f32x2
#pragma unroll
    for (int i = 0; i < 4; i++)
#pragma unroll
        for (int j = 0; j < 4; j++) acc[i][j] = 0ull;

#pragma unroll 4
    for (int k = 0; k < D; k++) {
        float4 a = *(const float4*)&inT[k][l * 4];
        unsigned long long w0 = *(const unsigned long long*)&WsT[k][colBase + 0];
        unsigned long long w1 = *(const unsigned long long*)&WsT[k][colBase + 2];
        unsigned long long w2 = *(const unsigned long long*)&WsT[k][colBase + 4];
        unsigned long long w3 = *(const unsigned long long*)&WsT[k][colBase + 6];
        unsigned long long ax = bcast_x2(a.x), ay = bcast_x2(a.y);
        unsigned long long az = bcast_x2(a.z), aw = bcast_x2(a.w);
        fma_x2(acc[0][0], ax, w0); fma_x2(acc[0][1], ax, w1);
        fma_x2(acc[0][2], ax, w2); fma_x2(acc[0][3], ax, w3);
        fma_x2(acc[1][0], ay, w0); fma_x2(acc[1][1], ay, w1);
        fma_x2(acc[1][2], ay, w2); fma_x2(acc[1][3], ay, w3);
        fma_x2(acc[2][0], az, w0); fma_x2(acc[2][1], az, w1);
        fma_x2(acc[2][2], az, w2); fma_x2(acc[2][3], az, w3);
        fma_x2(acc[3][0], aw, w0); fma_x2(acc[3][1], aw, w1);
        fma_x2(acc[3][2], aw, w2); fma_x2(acc[3][3], aw, w3);
    }

#pragma unroll
    for (int i = 0; i < 4; i++) {
        int orow = row0 + l * 4 + i;
        if (orow < N_NODES) {
            __half2 o[4];
#pragma unroll
            for (int j = 0; j < 4; j++) {
                float2 v = unpack_x2(acc[i][j]);
                o[j] = __floats2half2_rn(v.x + bs[colBase + 2 * j],
                                         v.y + bs[colBase + 2 * j + 1]);
            }
            *(uint4*)&out[(size_t)orow * 32 + colBase / 2] = *(const uint4*)o;
        }
    }
}

// ============================ aggregation kernels ============================

__global__ __launch_bounds__(256) void agg_kernel(const __half2* __restrict__ m,
                                                  __half2* __restrict__ out) {
    int node = (blockIdx.x * blockDim.x + threadIdx.x) >> 5;
    int l = threadIdx.x & 31;
    if (node >= N_NODES) return;
    int start = g_rowptr[node];
    int n = g_cnt[node];
    float a0 = 0.f, a1 = 0.f, b0 = 0.f, b1 = 0.f;
    float c0 = 0.f, c1 = 0.f, d0 = 0.f, d1 = 0.f;
    int k = 0;
    for (; k + 4 <= n; k += 4) {
        int s0 = __ldg(g_eidx + start + k + 0);
        int s1 = __ldg(g_eidx + start + k + 1);
        int s2 = __ldg(g_eidx + start + k + 2);
        int s3 = __ldg(g_eidx + start + k + 3);
        float2 v0 = __half22float2(__ldg(m + (size_t)s0 * 32 + l));
        float2 v1 = __half22float2(__ldg(m + (size_t)s1 * 32 + l));
        float2 v2 = __half22float2(__ldg(m + (size_t)s2 * 32 + l));
        float2 v3 = __half22float2(__ldg(m + (size_t)s3 * 32 + l));
        a0 += v0.x; a1 += v0.y;
        b0 += v1.x; b1 += v1.y;
        c0 += v2.x; c1 += v2.y;
        d0 += v3.x; d1 += v3.y;
    }
    for (; k < n; k++) {
        int s = __ldg(g_eidx + start + k);
        float2 v = __half22float2(__ldg(m + (size_t)s * 32 + l));
        a0 += v.x; a1 += v.y;
    }
    float v0 = (a0 + b0) + (c0 + d0);
    float v1 = (a1 + b1) + (c1 + d1);
    out[(size_t)node * 32 + l] = __floats2half2_rn(tanhf(v0), tanhf(v1));
}

__global__ __launch_bounds__(256) void agg_rsum_kernel(const __half2* __restrict__ m) {
    int node = (blockIdx.x * blockDim.x + threadIdx.x) >> 5;
    int l = threadIdx.x & 31;
    if (node >= N_NODES) return;
    int start = g_rowptr[node];
    int n = g_cnt[node];
    float a0 = 0.f, a1 = 0.f, b0 = 0.f, b1 = 0.f;
    float c0 = 0.f, c1 = 0.f, d0 = 0.f, d1 = 0.f;
    int k = 0;
    for (; k + 4 <= n; k += 4) {
        int s0 = __ldg(g_eidx + start + k + 0);
        int s1 = __ldg(g_eidx + start + k + 1);
        int s2 = __ldg(g_eidx + start + k + 2);
        int s3 = __ldg(g_eidx + start + k + 3);
        float2 v0 = __half22float2(__ldg(m + (size_t)s0 * 32 + l));
        float2 v1 = __half22float2(__ldg(m + (size_t)s1 * 32 + l));
        float2 v2 = __half22float2(__ldg(m + (size_t)s2 * 32 + l));
        float2 v3 = __half22float2(__ldg(m + (size_t)s3 * 32 + l));
        a0 += v0.x; a1 += v0.y;
        b0 += v1.x; b1 += v1.y;
        c0 += v2.x; c1 += v2.y;
        d0 += v3.x; d1 += v3.y;
    }
    for (; k < n; k++) {
        int s = __ldg(g_eidx + start + k);
        float2 v = __half22float2(__ldg(m + (size_t)s * 32 + l));
        a0 += v.x; a1 += v.y;
    }
    float v0 = (a0 + b0) + (c0 + d0);
    float v1 = (a1 + b1) + (c1 + d1);
    float s = tanhf(v0) * g_ws[2 * l] + tanhf(v1) * g_ws[2 * l + 1];
#pragma unroll
    for (int off = 16; off; off >>= 1) s += __shfl_down_sync(0xffffffffu, s, off);
    if (l == 0) g_r[node] = s + g_bsum[0];
}

// final: per node, sum r over incoming edges (CSR), bin by graph
__global__ __launch_bounds__(256) void final_kernel(const int* __restrict__ n2g,
                                                    float* __restrict__ out) {
    __shared__ float bins[8];
    int t = threadIdx.x;
    if (t < 8) bins[t] = 0.f;
    __syncthreads();
    int node = (blockIdx.x * blockDim.x + t) >> 5;
    int l = t & 31;
    if (node < N_NODES) {
        int start = g_rowptr[node], n = g_cnt[node];
        float s = 0.f;
        for (int e = l; e < n; e += 32) s += __ldg(g_r + __ldg(g_eidx + start + e));
#pragma unroll
        for (int off = 16; off; off >>= 1) s += __shfl_down_sync(0xffffffffu, s, off);
        if (l == 0) atomicAdd(&bins[__ldg(n2g + node)], s);
    }
    __syncthreads();
    if (t < 8) atomicAdd(&out[t], bins[t]);
}

// ============================ launch ============================

extern "C" void kernel_launch(void* const* d_in, const int* in_sizes, int n_in,
                              void* d_out, int out_size) {
    const float* x   = (const float*)d_in[0];
    const float* W1  = (const float*)d_in[1];
    const float* b1  = (const float*)d_in[2];
    const float* W2  = (const float*)d_in[3];
    const float* b2  = (const float*)d_in[4];
    const float* W3  = (const float*)d_in[5];
    const float* b3  = (const float*)d_in[6];
    const int*   src = (const int*)d_in[7];
    const int*   dst = (const int*)d_in[8];
    const int*   n2g = (const int*)d_in[9];
    float* out = (float*)d_out;

    int E = in_sizes[7];

    int nb_edges = (E + 255) / 256;
    int gemm_blocks = (N_NODES + 127) / 128;
    int warp_blocks = (N_NODES * 32 + 255) / 256;
    int init_blocks = 1 + (N_NODES + 255) / 256;

    __half* mH;  __half* hH;
    cudaGetSymbolAddress((void**)&mH, g_mH);
    cudaGetSymbolAddress((void**)&hH, g_hH);

    if (g_streamOk) {
        // fork: gemm1 on side stream, CSR build on main stream
        cudaEventRecord(g_evFork, 0);
        cudaStreamWaitEvent(g_s2, g_evFork, 0);
        gemm_rb_kernel<false><<<gemm_blocks, 256, 0, g_s2>>>(x, W1, b1, (__half2*)mH);
        cudaEventRecord(g_evJoin, g_s2);

        init_kernel<<<init_blocks, 256>>>(W3, b3, out, out_size);
        degree_kernel<<<nb_edges, 256>>>(dst, E);
        scanapply_kernel<<<NCHUNK, 256>>>();
        fill_kernel<<<nb_edges, 256>>>(src, dst, E);

        cudaStreamWaitEvent(0, g_evJoin, 0);   // join before agg1
    } else {
        init_kernel<<<init_blocks, 256>>>(W3, b3, out, out_size);
        degree_kernel<<<nb_edges, 256>>>(dst, E);
        scanapply_kernel<<<NCHUNK, 256>>>();
        fill_kernel<<<nb_edges, 256>>>(src, dst, E);
        gemm_rb_kernel<false><<<gemm_blocks, 256>>>(x, W1, b1, (__half2*)mH);
    }

    agg_kernel<<<warp_blocks, 256>>>((const __half2*)mH, (__half2*)hH);
    gemm_rb_kernel<true><<<gemm_blocks, 256>>>(hH, W2, b2, (__half2*)mH);
    agg_rsum_kernel<<<warp_blocks, 256>>>((const __half2*)mH);
    final_kernel<<<warp_blocks, 256>>>(n2g, out);
}

// round 9
// speedup vs baseline: 1.4627x; 1.0365x over previous
#include <cuda_runtime.h>
#include <cuda_fp16.h>
#include <math.h>

#define N_NODES 100000
#define D 64
#define E_MAX 1600000
#define CHUNK 1024
#define NCHUNK ((N_NODES + CHUNK - 1) / CHUNK)   // 98

// ---- scratch (__device__ globals: allocation-free per harness rules) ----
__device__ __half g_mH[(size_t)N_NODES * D];    // fp16 message buffer (GEMM out)
__device__ __half g_hH[(size_t)N_NODES * D];    // fp16 hidden state
__device__ float  g_r[N_NODES];                 // per-node scalar (layer-3 collapse)
__device__ float  g_ws[D];                      // colsum(W3)
__device__ float  g_bsum[1];                    // sum(b3)
__device__ int    g_cnt[N_NODES];               // zeroed by final_kernel (prev call)
__device__ int    g_rowptr[N_NODES];
__device__ int    g_cursor[N_NODES];
__device__ int    g_eidx[E_MAX];
__device__ int    g_csum[128];                  // lookback slots; zeroed by final_kernel

// ---- side stream + events for graph fork (created at load; never freed) ----
static cudaStream_t g_s2;
static cudaEvent_t  g_evFork, g_evJoin;
static bool g_streamOk = [](){
    if (cudaStreamCreateWithFlags(&g_s2, cudaStreamNonBlocking) != cudaSuccess) return false;
    if (cudaEventCreateWithFlags(&g_evFork, cudaEventDisableTiming) != cudaSuccess) return false;
    if (cudaEventCreateWithFlags(&g_evJoin, cudaEventDisableTiming) != cudaSuccess) return false;
    return true;
}();

// ---- PDL: grid-dependency sync at kernel entry ----
__device__ __forceinline__ void dep_sync() {
#if defined(__CUDA_ARCH__) && __CUDA_ARCH__ >= 900
    cudaGridDependencySynchronize();
#endif
}

// ---- packed f32x2 helpers (Blackwell FFMA2; PTX-only) ----
__device__ __forceinline__ void fma_x2(unsigned long long& acc,
                                       unsigned long long a, unsigned long long b) {
    asm("fma.rn.f32x2 %0, %1, %2, %0;" : "+l"(acc) : "l"(a), "l"(b));
}
__device__ __forceinline__ unsigned long long bcast_x2(float v) {
    unsigned long long r;
    asm("mov.b64 %0, {%1, %1};" : "=l"(r) : "r"(__float_as_uint(v)));
    return r;
}
__device__ __forceinline__ float2 unpack_x2(unsigned long long v) {
    unsigned int lo, hi;
    asm("mov.b64 {%0, %1}, %2;" : "=r"(lo), "=r"(hi) : "l"(v));
    return make_float2(__uint_as_float(lo), __uint_as_float(hi));
}

// ============================ CSR build ============================

// block 0: constants + d_out zero; blocks 1..: degree histogram, 4 edges/thread.
__global__ void degree_kernel(const int4* __restrict__ dst4, int E4,
                              const float* __restrict__ W3, const float* __restrict__ b3,
                              float* __restrict__ out, int out_n) {
    dep_sync();
    int t = threadIdx.x;
    if (blockIdx.x == 0) {
        if (t < D) {
            float s = 0.f;
#pragma unroll
            for (int j = 0; j < D; j++) s += W3[j * D + t];
            g_ws[t] = s;
        } else if (t == D) {
            float bs = 0.f;
#pragma unroll
            for (int j = 0; j < D; j++) bs += b3[j];
            g_bsum[0] = bs;
        } else if (t >= 96 && t < 96 + out_n) {
            out[t - 96] = 0.f;
        }
        return;
    }
    int i = (blockIdx.x - 1) * blockDim.x + t;
    if (i < E4) {
        int4 d = dst4[i];
        atomicAdd(&g_cnt[d.x], 1);
        atomicAdd(&g_cnt[d.y], 1);
        atomicAdd(&g_cnt[d.z], 1);
        atomicAdd(&g_cnt[d.w], 1);
    }
}

// single-pass exclusive scan with decoupled lookback (98 blocks, wave-1 resident)
__global__ __launch_bounds__(256) void scanapply_kernel() {
    dep_sync();
    int b = blockIdx.x, t = threadIdx.x;
    int base = b * CHUNK + t * 4;
    int c[4];
    int ts = 0;
#pragma unroll
    for (int i = 0; i < 4; i++) {
        int idx = base + i;
        c[i] = (idx < N_NODES) ? g_cnt[idx] : 0;
        ts += c[i];
    }
    int lane = t & 31, wid = t >> 5;
    int incl = ts;
#pragma unroll
    for (int d = 1; d < 32; d <<= 1) {
        int u = __shfl_up_sync(0xffffffffu, incl, d);
        if (lane >= d) incl += u;
    }
    __shared__ int wsum[8], woff[8];
    __shared__ int rsum[8];
    __shared__ int s_prefix;
    if (lane == 31) wsum[wid] = incl;
    __syncthreads();
    if (t == 0) {
        int acc = 0;
#pragma unroll
        for (int i = 0; i < 8; i++) { woff[i] = acc; acc += wsum[i]; }
        *(volatile int*)&g_csum[b] = acc + 1;   // publish (+1: 0 = not ready)
    }
    __syncthreads();
    int part = 0;
    if (t < b) {
        volatile int* p = &g_csum[t];
        int v;
        do { v = *p; } while (v == 0);
        part = v - 1;
    }
#pragma unroll
    for (int off = 16; off; off >>= 1) part += __shfl_down_sync(0xffffffffu, part, off);
    if (lane == 0) rsum[wid] = part;
    __syncthreads();
    if (t == 0) {
        int acc = 0;
#pragma unroll
        for (int i = 0; i < 8; i++) acc += rsum[i];
        s_prefix = acc;
    }
    __syncthreads();
    int excl = incl - ts + woff[wid] + s_prefix;
#pragma unroll
    for (int i = 0; i < 4; i++) {
        int idx = base + i;
        if (idx < N_NODES) { g_rowptr[idx] = excl; g_cursor[idx] = excl; }
        excl += c[i];
    }
}

__global__ void fill_kernel(const int* __restrict__ src, const int* __restrict__ dst, int E) {
    dep_sync();
    int e = blockIdx.x * blockDim.x + threadIdx.x;
    if (e < E) {
        int pos = atomicAdd(&g_cursor[dst[e]], 1);
        g_eidx[pos] = src[e];
    }
}

// ============================ f32x2 register-blocked GEMM ============================
template<bool HALF_IN>
__global__ __launch_bounds__(256) void gemm_rb_kernel(const void* __restrict__ in_,
                                                      const float* __restrict__ W,
                                                      const float* __restrict__ b,
                                                      __half2* __restrict__ out) {
    dep_sync();
    __shared__ float inT[D][128];        // 32KB, [k][row]
    __shared__ float WsT[D][D + 2];      // ~16.5KB, [k][col] (transposed, padded)
    __shared__ float bs[D];
    int t = threadIdx.x;
    for (int i = t; i < D * D; i += 256) {
        int j = i >> 6, k = i & 63;
        WsT[k][j] = W[i];
    }
    if (t < D) bs[t] = b[t];

    int row0 = blockIdx.x * 128;
    int r = t >> 1, half = t & 1;
    int grow = row0 + r;
    if (HALF_IN) {
        const __half2* inH = (const __half2*)in_ + (size_t)grow * 32 + half * 16;
        if (grow < N_NODES) {
#pragma unroll
            for (int i = 0; i < 16; i++) {
                float2 f = __half22float2(inH[i]);
                inT[half * 32 + 2 * i + 0][r] = f.x;
                inT[half * 32 + 2 * i + 1][r] = f.y;
            }
        } else {
#pragma unroll
            for (int i = 0; i < 32; i++) inT[half * 32 + i][r] = 0.f;
        }
    } else {
        const float4* inF = (const float4*)((const float*)in_ + (size_t)grow * D + half * 32);
        if (grow < N_NODES) {
#pragma unroll
            for (int i = 0; i < 8; i++) {
                float4 v = inF[i];
                inT[half * 32 + 4 * i + 0][r] = v.x;
                inT[half * 32 + 4 * i + 1][r] = v.y;
                inT[half * 32 + 4 * i + 2][r] = v.z;
                inT[half * 32 + 4 * i + 3][r] = v.w;
            }
        } else {
#pragma unroll
            for (int i = 0; i < 32; i++) inT[half * 32 + i][r] = 0.f;
        }
    }
    __syncthreads();

    int w = t >> 5, l = t & 31;
    int colBase = w * 8;
    unsigned long long acc[4][4];
#pragma unroll
    for (int i = 0; i < 4; i++)
#pragma unroll
        for (int j = 0; j < 4; j++) acc[i][j] = 0ull;

#pragma unroll 4
    for (int k = 0; k < D; k++) {
        float4 a = *(const float4*)&inT[k][l * 4];
        unsigned long long w0 = *(const unsigned long long*)&WsT[k][colBase + 0];
        unsigned long long w1 = *(const unsigned long long*)&WsT[k][colBase + 2];
        unsigned long long w2 = *(const unsigned long long*)&WsT[k][colBase + 4];
        unsigned long long w3 = *(const unsigned long long*)&WsT[k][colBase + 6];
        unsigned long long ax = bcast_x2(a.x), ay = bcast_x2(a.y);
        unsigned long long az = bcast_x2(a.z), aw = bcast_x2(a.w);
        fma_x2(acc[0][0], ax, w0); fma_x2(acc[0][1], ax, w1);
        fma_x2(acc[0][2], ax, w2); fma_x2(acc[0][3], ax, w3);
        fma_x2(acc[1][0], ay, w0); fma_x2(acc[1][1], ay, w1);
        fma_x2(acc[1][2], ay, w2); fma_x2(acc[1][3], ay, w3);
        fma_x2(acc[2][0], az, w0); fma_x2(acc[2][1], az, w1);
        fma_x2(acc[2][2], az, w2); fma_x2(acc[2][3], az, w3);
        fma_x2(acc[3][0], aw, w0); fma_x2(acc[3][1], aw, w1);
        fma_x2(acc[3][2], aw, w2); fma_x2(acc[3][3], aw, w3);
    }

#pragma unroll
    for (int i = 0; i < 4; i++) {
        int orow = row0 + l * 4 + i;
        if (orow < N_NODES) {
            __half2 o[4];
#pragma unroll
            for (int j = 0; j < 4; j++) {
                float2 v = unpack_x2(acc[i][j]);
                o[j] = __floats2half2_rn(v.x + bs[colBase + 2 * j],
                                         v.y + bs[colBase + 2 * j + 1]);
            }
            *(uint4*)&out[(size_t)orow * 32 + colBase / 2] = *(const uint4*)o;
        }
    }
}

// ============================ aggregation kernels ============================

__global__ __launch_bounds__(256) void agg_kernel(const __half2* __restrict__ m,
                                                  __half2* __restrict__ out) {
    dep_sync();
    int node = (blockIdx.x * blockDim.x + threadIdx.x) >> 5;
    int l = threadIdx.x & 31;
    if (node >= N_NODES) return;
    int start = g_rowptr[node];
    int n = g_cnt[node];
    float a0 = 0.f, a1 = 0.f, b0 = 0.f, b1 = 0.f;
    float c0 = 0.f, c1 = 0.f, d0 = 0.f, d1 = 0.f;
    int k = 0;
    for (; k + 4 <= n; k += 4) {
        int s0 = __ldg(g_eidx + start + k + 0);
        int s1 = __ldg(g_eidx + start + k + 1);
        int s2 = __ldg(g_eidx + start + k + 2);
        int s3 = __ldg(g_eidx + start + k + 3);
        float2 v0 = __half22float2(__ldg(m + (size_t)s0 * 32 + l));
        float2 v1 = __half22float2(__ldg(m + (size_t)s1 * 32 + l));
        float2 v2 = __half22float2(__ldg(m + (size_t)s2 * 32 + l));
        float2 v3 = __half22float2(__ldg(m + (size_t)s3 * 32 + l));
        a0 += v0.x; a1 += v0.y;
        b0 += v1.x; b1 += v1.y;
        c0 += v2.x; c1 += v2.y;
        d0 += v3.x; d1 += v3.y;
    }
    for (; k < n; k++) {
        int s = __ldg(g_eidx + start + k);
        float2 v = __half22float2(__ldg(m + (size_t)s * 32 + l));
        a0 += v.x; a1 += v.y;
    }
    float v0 = (a0 + b0) + (c0 + d0);
    float v1 = (a1 + b1) + (c1 + d1);
    out[(size_t)node * 32 + l] = __floats2half2_rn(tanhf(v0), tanhf(v1));
}

__global__ __launch_bounds__(256) void agg_rsum_kernel(const __half2* __restrict__ m) {
    dep_sync();
    int node = (blockIdx.x * blockDim.x + threadIdx.x) >> 5;
    int l = threadIdx.x & 31;
    if (node >= N_NODES) return;
    int start = g_rowptr[node];
    int n = g_cnt[node];
    float a0 = 0.f, a1 = 0.f, b0 = 0.f, b1 = 0.f;
    float c0 = 0.f, c1 = 0.f, d0 = 0.f, d1 = 0.f;
    int k = 0;
    for (; k + 4 <= n; k += 4) {
        int s0 = __ldg(g_eidx + start + k + 0);
        int s1 = __ldg(g_eidx + start + k + 1);
        int s2 = __ldg(g_eidx + start + k + 2);
        int s3 = __ldg(g_eidx + start + k + 3);
        float2 v0 = __half22float2(__ldg(m + (size_t)s0 * 32 + l));
        float2 v1 = __half22float2(__ldg(m + (size_t)s1 * 32 + l));
        float2 v2 = __half22float2(__ldg(m + (size_t)s2 * 32 + l));
        float2 v3 = __half22float2(__ldg(m + (size_t)s3 * 32 + l));
        a0 += v0.x; a1 += v0.y;
        b0 += v1.x; b1 += v1.y;
        c0 += v2.x; c1 += v2.y;
        d0 += v3.x; d1 += v3.y;
    }
    for (; k < n; k++) {
        int s = __ldg(g_eidx + start + k);
        float2 v = __half22float2(__ldg(m + (size_t)s * 32 + l));
        a0 += v.x; a1 += v.y;
    }
    float v0 = (a0 + b0) + (c0 + d0);
    float v1 = (a1 + b1) + (c1 + d1);
    float s = tanhf(v0) * g_ws[2 * l] + tanhf(v1) * g_ws[2 * l + 1];
#pragma unroll
    for (int off = 16; off; off >>= 1) s += __shfl_down_sync(0xffffffffu, s, off);
    if (l == 0) g_r[node] = s + g_bsum[0];
}

// final: per node, sum r over incoming edges (CSR, degree via rowptr diff),
// bin by graph. Also cleans g_cnt/g_csum for the next replay.
__global__ __launch_bounds__(256) void final_kernel(const int* __restrict__ n2g,
                                                    float* __restrict__ out, int E) {
    dep_sync();
    __shared__ float bins[8];
    int t = threadIdx.x;
    if (t < 8) bins[t] = 0.f;
    __syncthreads();
    int node = (blockIdx.x * blockDim.x + t) >> 5;
    int l = t & 31;
    if (node < N_NODES) {
        int start = g_rowptr[node];
        int end = (node + 1 < N_NODES) ? __ldg(g_rowptr + node + 1) : E;
        float s = 0.f;
        for (int e = start + l; e < end; e += 32) s += __ldg(g_r + __ldg(g_eidx + e));
#pragma unroll
        for (int off = 16; off; off >>= 1) s += __shfl_down_sync(0xffffffffu, s, off);
        if (l == 0) atomicAdd(&bins[__ldg(n2g + node)], s);
    }
    __syncthreads();
    if (t < 8) atomicAdd(&out[t], bins[t]);
    // cleanup for next call (final never reads g_cnt / g_csum)
    for (int i = blockIdx.x * blockDim.x + t; i < N_NODES; i += gridDim.x * blockDim.x)
        g_cnt[i] = 0;
    if (blockIdx.x == 0 && t >= 128 && t < 256) g_csum[t - 128] = 0;
}

// ============================ launch ============================

template<typename... Args>
static void launch_pdl(void* func, dim3 grid, dim3 block, cudaStream_t s, Args*... args) {
    void* argv[] = { (void*)args... };
    cudaLaunchConfig_t cfg = {};
    cfg.gridDim = grid; cfg.blockDim = block; cfg.stream = s;
    cudaLaunchAttribute attr[1];
    attr[0].id = cudaLaunchAttributeProgrammaticStreamSerialization;
    attr[0].val.programmaticStreamSerializationAllowed = 1;
    cfg.attrs = attr; cfg.numAttrs = 1;
    cudaLaunchKernelExC(&cfg, func, argv);
}

extern "C" void kernel_launch(void* const* d_in, const int* in_sizes, int n_in,
                              void* d_out, int out_size) {
    const float* x   = (const float*)d_in[0];
    const float* W1  = (const float*)d_in[1];
    const float* b1  = (const float*)d_in[2];
    const float* W2  = (const float*)d_in[3];
    const float* b2  = (const float*)d_in[4];
    const float* W3  = (const float*)d_in[5];
    const float* b3  = (const float*)d_in[6];
    const int*   src = (const int*)d_in[7];
    const int*   dst = (const int*)d_in[8];
    const int*   n2g = (const int*)d_in[9];
    float* out = (float*)d_out;

    int E  = in_sizes[7];
    int E4 = E / 4;                       // E = 1.6M, divisible by 4
    int nb_edges = (E + 255) / 256;
    int deg_blocks = 1 + (E4 + 255) / 256;
    int gemm_blocks = (N_NODES + 127) / 128;
    int warp_blocks = (N_NODES * 32 + 255) / 256;

    __half* mH;  __half* hH;
    cudaGetSymbolAddress((void**)&mH, g_mH);
    cudaGetSymbolAddress((void**)&hH, g_hH);

    const void* xv = x;  const void* hv = hH;
    __half2* mH2 = (__half2*)mH;
    __half2* hH2 = (__half2*)hH;
    const __half2* mH2c = (const __half2*)mH;
    const int4* dst4 = (const int4*)dst;

    if (g_streamOk) {
        cudaEventRecord(g_evFork, 0);
        cudaStreamWaitEvent(g_s2, g_evFork, 0);
        gemm_rb_kernel<false><<<gemm_blocks, 256, 0, g_s2>>>(x, W1, b1, mH2);
        cudaEventRecord(g_evJoin, g_s2);

        launch_pdl((void*)degree_kernel, deg_blocks, 256, 0,
                   &dst4, &E4, &W3, &b3, &out, &out_size);
        launch_pdl((void*)scanapply_kernel, NCHUNK, 256, 0);
        launch_pdl((void*)fill_kernel, nb_edges, 256, 0, &src, &dst, &E);

        cudaStreamWaitEvent(0, g_evJoin, 0);   // join before agg1
    } else {
        degree_kernel<<<deg_blocks, 256>>>(dst4, E4, W3, b3, out, out_size);
        scanapply_kernel<<<NCHUNK, 256>>>();
        fill_kernel<<<nb_edges, 256>>>(src, dst, E);
        gemm_rb_kernel<false><<<gemm_blocks, 256>>>(x, W1, b1, mH2);
    }

    launch_pdl((void*)agg_kernel, warp_blocks, 256, 0, &mH2c, &hH2);
    launch_pdl((void*)gemm_rb_kernel<true>, gemm_blocks, 256, 0, &hv, &W2, &b2, &mH2);
    launch_pdl((void*)agg_rsum_kernel, warp_blocks, 256, 0, &mH2c);
    launch_pdl((void*)final_kernel, warp_blocks, 256, 0, &n2g, &out, &E);
}